// round 10
// baseline (speedup 1.0000x reference)
#include <cuda_runtime.h>
#include <cuda_fp16.h>
#include <cstdint>

#define HW 4096
#define CD 64
#define BM 64
#define BN 64
#define NT (HW / BN)
#define NB 8
#define RB 72
#define RBB 144
#define KHI_BYTES (64 * RBB)          // 9216: Khi fp16 tile, RBB-padded rows
#define K8_BYTES  8192                // int8 cross B-fragments for one tile
#define KVBUF (KHI_BYTES + K8_BYTES)  // 17408
#define QOFF (2 * KVBUF)              // 34816
#define SMEM_TOTAL (QOFF + KHI_BYTES) // 44032

#define S1F (6.0f / 127.0f)           // hi quant scale
#define S2F (12.0f / 127.0f)          // (lo*4096) quant scale
#define SCALE_CROSS (S1F * S2F * (1.0f / 4096.0f))

__device__ __align__(16) __half g_FH[NB * CD * HW];            // fp16(x)
__device__ __align__(16) uint4 g_Q8[NB * 256 * 4 * 32];        // A-frags [n][qb][ch][lane]
__device__ __align__(16) uint2 g_K8[NB * 512 * 4 * 32];        // B-frags [n][kb][ch][lane]

__device__ __forceinline__ uint32_t smem_u32(const void* p) {
    uint32_t a;
    asm("{ .reg .u64 t; cvta.to.shared.u64 t, %1; cvt.u32.u64 %0, t; }" : "=r"(a) : "l"(p));
    return a;
}
__device__ __forceinline__ void ldsm4(uint32_t addr, uint32_t* r) {
    asm volatile("ldmatrix.sync.aligned.m8n8.x4.shared.b16 {%0,%1,%2,%3}, [%4];"
                 : "=r"(r[0]), "=r"(r[1]), "=r"(r[2]), "=r"(r[3]) : "r"(addr));
}
__device__ __forceinline__ void ldsm4t(uint32_t addr, uint32_t* r) {
    asm volatile("ldmatrix.sync.aligned.m8n8.x4.trans.shared.b16 {%0,%1,%2,%3}, [%4];"
                 : "=r"(r[0]), "=r"(r[1]), "=r"(r[2]), "=r"(r[3]) : "r"(addr));
}
__device__ __forceinline__ void mma_f16(float* d, const uint32_t* a, uint32_t b0, uint32_t b1) {
    asm volatile(
        "mma.sync.aligned.m16n8k16.row.col.f32.f16.f16.f32 "
        "{%0,%1,%2,%3}, {%4,%5,%6,%7}, {%8,%9}, {%0,%1,%2,%3};"
        : "+f"(d[0]), "+f"(d[1]), "+f"(d[2]), "+f"(d[3])
        : "r"(a[0]), "r"(a[1]), "r"(a[2]), "r"(a[3]), "r"(b0), "r"(b1));
}
__device__ __forceinline__ void mma_s8(int32_t* d, const uint32_t* a, uint32_t b0, uint32_t b1) {
    asm volatile(
        "mma.sync.aligned.m16n8k32.row.col.s32.s8.s8.s32 "
        "{%0,%1,%2,%3}, {%4,%5,%6,%7}, {%8,%9}, {%0,%1,%2,%3};"
        : "+r"(d[0]), "+r"(d[1]), "+r"(d[2]), "+r"(d[3])
        : "r"(a[0]), "r"(a[1]), "r"(a[2]), "r"(a[3]), "r"(b0), "r"(b1));
}
#define CP16(dst, src) asm volatile("cp.async.cg.shared.global [%0], [%1], 16;" :: "r"(dst), "l"(src))
#define CP_COMMIT()    asm volatile("cp.async.commit_group;" ::: "memory")
#define CP_WAIT1()     asm volatile("cp.async.wait_group 1;" ::: "memory")
#define CP_WAIT2()     asm volatile("cp.async.wait_group 2;" ::: "memory")

__device__ __forceinline__ uint32_t pkf16(float a, float b) {
    uint32_t r;
    asm("cvt.rn.f16x2.f32 %0, %1, %2;" : "=r"(r) : "f"(b), "f"(a));
    return r;
}
__device__ __forceinline__ int qclamp(float v) {
    int r = __float2int_rn(v);
    return max(-127, min(127, r));
}
// x -> (hi fp16 value as float, lo residual)
__device__ __forceinline__ void hilo(float x, float& h, float& l) {
    __half hh = __float2half_rn(x);
    h = __half2float(hh);
    l = x - h;
}
// quantized byte for concatenated-A column ac (0..127): <64 -> hi8, >=64 -> lo8*4096
__device__ __forceinline__ uint32_t abyte(const float* Xn, int ac, int row) {
    float h, l;
    if (ac < 64) {
        hilo(Xn[(size_t)ac * HW + row], h, l);
        return (uint32_t)(qclamp(h * (1.0f / S1F)) & 0xff);
    }
    hilo(Xn[(size_t)(ac - 64) * HW + row], h, l);
    return (uint32_t)(qclamp(l * 4096.0f * (1.0f / S2F)) & 0xff);
}
// quantized byte for concatenated-B row br (0..127): <64 -> lo8*4096, >=64 -> hi8
__device__ __forceinline__ uint32_t bbyte(const float* Xn, int br, int key) {
    float h, l;
    if (br < 64) {
        hilo(Xn[(size_t)br * HW + key], h, l);
        return (uint32_t)(qclamp(l * 4096.0f * (1.0f / S2F)) & 0xff);
    }
    hilo(Xn[(size_t)(br - 64) * HW + key], h, l);
    return (uint32_t)(qclamp(h * (1.0f / S1F)) & 0xff);
}

// ---------------- pre-kernel 1: fp16(x) array ----------------
__global__ __launch_bounds__(256) void convert_kernel(const float* __restrict__ X) {
    size_t i = (size_t)blockIdx.x * 256 + threadIdx.x;
    float4 v = reinterpret_cast<const float4*>(X)[i];
    __half hx = __float2half_rn(v.x), hy = __float2half_rn(v.y);
    __half hz = __float2half_rn(v.z), hw = __float2half_rn(v.w);
    uint2 h;
    h.x = (uint32_t)__half_as_ushort(hx) | ((uint32_t)__half_as_ushort(hy) << 16);
    h.y = (uint32_t)__half_as_ushort(hz) | ((uint32_t)__half_as_ushort(hw) << 16);
    reinterpret_cast<uint2*>(g_FH)[i] = h;
}

// ---------------- pre-kernel 2: int8 B-fragments (K side) ----------------
__global__ __launch_bounds__(256) void fragk_kernel(const float* __restrict__ X) {
    int t = blockIdx.x * 256 + threadIdx.x;   // [n][kb][ch][lane]
    int lane = t & 31, ch = (t >> 5) & 3, kb = (t >> 7) & 511, n = t >> 16;
    const float* Xn = X + (size_t)n * CD * HW;
    int key = kb * 8 + (lane >> 2);
    int r0 = 32 * ch + (lane & 3) * 4;
    uint32_t b0 = 0, b1 = 0;
#pragma unroll
    for (int j = 0; j < 4; j++) {
        b0 |= bbyte(Xn, r0 + j, key) << (8 * j);
        b1 |= bbyte(Xn, r0 + 16 + j, key) << (8 * j);
    }
    g_K8[t] = make_uint2(b0, b1);
}

// ---------------- pre-kernel 3: int8 A-fragments (Q side) ----------------
__global__ __launch_bounds__(256) void fragq_kernel(const float* __restrict__ X) {
    int t = blockIdx.x * 256 + threadIdx.x;   // [n][qb][ch][lane]
    int lane = t & 31, ch = (t >> 5) & 3, qb = (t >> 7) & 255, n = t >> 15;
    const float* Xn = X + (size_t)n * CD * HW;
    int row = qb * 16 + (lane >> 2);
    int c0 = 32 * ch + (lane & 3) * 4;
    uint32_t a0 = 0, a1 = 0, a2 = 0, a3 = 0;
#pragma unroll
    for (int j = 0; j < 4; j++) {
        a0 |= abyte(Xn, c0 + j, row) << (8 * j);
        a1 |= abyte(Xn, c0 + j, row + 8) << (8 * j);
        a2 |= abyte(Xn, c0 + 16 + j, row) << (8 * j);
        a3 |= abyte(Xn, c0 + 16 + j, row + 8) << (8 * j);
    }
    g_Q8[t] = make_uint4(a0, a1, a2, a3);
}

// ---------------- main attention kernel ----------------
__global__ __launch_bounds__(128, 4) void attn_mma(float* __restrict__ out) {
    extern __shared__ __align__(128) char SM[];
    const uint32_t smb = smem_u32(SM);

    const int n = blockIdx.y;
    const int q0 = blockIdx.x * BM;
    const int tid = threadIdx.x;
    const int lane = tid & 31;
    const int wid = tid >> 5;          // warp owns q rows wid*16 .. +15
    const int g = lane >> 2, tq = lane & 3;
    const int r8 = lane & 7, sel = lane >> 3;

    const char* FHn = (const char*)(g_FH + (size_t)n * CD * HW);
    const char* K8n = (const char*)(g_K8 + (size_t)n * 512 * 4 * 32);

    // stage one KV tile: Khi fp16 (RBB rows) + int8 B-fragments
    auto stage = [&](uint32_t bufoff, int t) {
        int col0 = t * BN;
#pragma unroll
        for (int i = 0; i < 4; i++) {
            int idx = i * 128 + tid;
            int cc = idx >> 3, ch = idx & 7;
            CP16(smb + bufoff + cc * RBB + ch * 16,
                 FHn + ((size_t)cc * HW + col0 + ch * 8) * 2);
        }
        const char* ksrc = K8n + (size_t)t * K8_BYTES + tid * 64;
        uint32_t kdst = smb + bufoff + KHI_BYTES + tid * 64;
#pragma unroll
        for (int j = 0; j < 4; j++) CP16(kdst + j * 16, ksrc + j * 16);
    };

    // Q hi tile -> QOFF
    {
#pragma unroll
        for (int i = 0; i < 4; i++) {
            int idx = i * 128 + tid;
            int cc = idx >> 3, ch = idx & 7;
            CP16(smb + QOFF + cc * RBB + ch * 16,
                 FHn + ((size_t)cc * HW + q0 + ch * 8) * 2);
        }
    }
    CP_COMMIT();
    stage(0, 0);     CP_COMMIT();
    stage(KVBUF, 1); CP_COMMIT();
    CP_WAIT2();      // Q resident
    __syncthreads();

    // Q A-fragments: fp16 hi (ldmatrix.trans) + int8 (direct LDG, frag-ready)
    uint32_t qh[4][4];
    {
        const uint32_t qb2 = smb + QOFF;
        const uint32_t lo = ((sel >> 1) * 8 + r8) * RBB + (wid * 16 + (sel & 1) * 8) * 2;
#pragma unroll
        for (int ch = 0; ch < 4; ch++) ldsm4t(qb2 + ch * 16 * RBB + lo, qh[ch]);
    }
    uint32_t qa[4][4];
    {
        int qb = blockIdx.x * 4 + wid;
        const uint4* qsrc = g_Q8 + ((size_t)((n * 256 + qb) * 4)) * 32 + lane;
#pragma unroll
        for (int ch = 0; ch < 4; ch++) {
            uint4 v = qsrc[ch * 32];
            qa[ch][0] = v.x; qa[ch][1] = v.y; qa[ch][2] = v.z; qa[ch][3] = v.w;
        }
    }

    const int row_a = wid * 16 + g, row_b = row_a + 8;

    float o[8][4];
#pragma unroll
    for (int j = 0; j < 8; j++)
#pragma unroll
        for (int r = 0; r < 4; r++) o[j][r] = 0.f;
    float la = 0.f, lb = 0.f;
    float ma = -1e30f, mb = -1e30f;

    const uint32_t g1off = ((sel & 1) * 8 + r8) * RBB + ((sel >> 1) * 8) * 2;
    const uint32_t g2off = ((sel >> 1) * 8 + r8) * RBB + ((sel & 1) * 8) * 2;

    for (int t = 0; t < NT; t++) {
        CP_WAIT1();
        __syncthreads();
        const uint32_t vboff = (uint32_t)(t & 1) * KVBUF;
        const uint32_t vb = smb + vboff;
        const char* SMv = SM + vboff;

        // ---- cross terms: int8 k32 MMAs (exact), c[kb] <-> key-block kb ----
        int32_t c[8][4];
#pragma unroll
        for (int j = 0; j < 8; j++)
#pragma unroll
            for (int r = 0; r < 4; r++) c[j][r] = 0;
#pragma unroll
        for (int kb = 0; kb < 8; kb += 2) {
            const char* p0 = SMv + KHI_BYTES + kb * 1024 + lane * 8;
            const char* p1 = p0 + 1024;
            uint2 f0[4], f1[4];
#pragma unroll
            for (int ch = 0; ch < 4; ch++) {
                f0[ch] = *(const uint2*)(p0 + ch * 256);
                f1[ch] = *(const uint2*)(p1 + ch * 256);
            }
#pragma unroll
            for (int ch = 0; ch < 4; ch++) {
                mma_s8(c[kb], qa[ch], f0[ch].x, f0[ch].y);
                mma_s8(c[kb + 1], qa[ch], f1[ch].x, f1[ch].y);
            }
        }
        float s[8][4];
#pragma unroll
        for (int j = 0; j < 8; j++)
#pragma unroll
            for (int r = 0; r < 4; r++) s[j][r] = (float)c[j][r] * SCALE_CROSS;

        // ---- hi*hi: fp16 MMAs accumulate on top of cross ----
#pragma unroll
        for (int ch = 0; ch < 4; ch++) {
            const uint32_t base = vb + g1off + ch * 16 * RBB;
#pragma unroll
            for (int kp = 0; kp < 2; kp++) {
                const uint32_t ka = base + (2 * kp) * 32;
                uint32_t bh0[4], bh1[4];
                ldsm4t(ka, bh0);
                ldsm4t(ka + 32, bh1);
                mma_f16(s[4 * kp], qh[ch], bh0[0], bh0[1]);
                mma_f16(s[4 * kp + 1], qh[ch], bh0[2], bh0[3]);
                mma_f16(s[4 * kp + 2], qh[ch], bh1[0], bh1[1]);
                mma_f16(s[4 * kp + 3], qh[ch], bh1[2], bh1[3]);
            }
        }

        // ---- online softmax (FA2), rows warp-local ----
        float am = -1e30f, bm = -1e30f;
#pragma unroll
        for (int f = 0; f < 8; f++) {
            am = fmaxf(am, fmaxf(s[f][0], s[f][1]));
            bm = fmaxf(bm, fmaxf(s[f][2], s[f][3]));
        }
        am = fmaxf(am, __shfl_xor_sync(~0u, am, 1));
        am = fmaxf(am, __shfl_xor_sync(~0u, am, 2));
        bm = fmaxf(bm, __shfl_xor_sync(~0u, bm, 1));
        bm = fmaxf(bm, __shfl_xor_sync(~0u, bm, 2));
        if (__any_sync(~0u, (am > ma) | (bm > mb))) {
            float man = fmaxf(ma, am), mbn = fmaxf(mb, bm);
            float ca = __expf(ma - man), cb = __expf(mb - mbn);
            ma = man;
            mb = mbn;
            la *= ca;
            lb *= cb;
#pragma unroll
            for (int j = 0; j < 8; j++) {
                o[j][0] *= ca;
                o[j][1] *= ca;
                o[j][2] *= cb;
                o[j][3] *= cb;
            }
        }

        uint32_t pf[4][4];
#pragma unroll
        for (int kc = 0; kc < 4; kc++) {
            float e0 = __expf(s[2 * kc][0] - ma), e1 = __expf(s[2 * kc][1] - ma);
            float e2 = __expf(s[2 * kc][2] - mb), e3 = __expf(s[2 * kc][3] - mb);
            float e4 = __expf(s[2 * kc + 1][0] - ma), e5 = __expf(s[2 * kc + 1][1] - ma);
            float e6 = __expf(s[2 * kc + 1][2] - mb), e7 = __expf(s[2 * kc + 1][3] - mb);
            la += e0 + e1 + e4 + e5;
            lb += e2 + e3 + e6 + e7;
            pf[kc][0] = pkf16(e0, e1);
            pf[kc][1] = pkf16(e2, e3);
            pf[kc][2] = pkf16(e4, e5);
            pf[kc][3] = pkf16(e6, e7);
        }

        // ---- gemm2: O += P Vhi, fp16 single pass ----
#pragma unroll
        for (int kc = 0; kc < 4; kc++) {
#pragma unroll
            for (int mp = 0; mp < 2; mp++) {
                const uint32_t ba = vb + g2off + (2 * mp) * 16 * RBB + kc * 32;
                const uint32_t bb = ba + 16 * RBB;
                uint32_t bfa[4], bfb[4];
                ldsm4(ba, bfa);
                ldsm4(bb, bfb);
                mma_f16(o[4 * mp], pf[kc], bfa[0], bfa[1]);
                mma_f16(o[4 * mp + 1], pf[kc], bfa[2], bfa[3]);
                mma_f16(o[4 * mp + 2], pf[kc], bfb[0], bfb[1]);
                mma_f16(o[4 * mp + 3], pf[kc], bfb[2], bfb[3]);
            }
        }
        __syncthreads();
        if (t + 2 < NT) stage(vboff, t + 2);
        CP_COMMIT();
    }

    // ---- epilogue: rows warp-local -> normalize + store ----
    la += __shfl_xor_sync(~0u, la, 1);
    la += __shfl_xor_sync(~0u, la, 2);
    lb += __shfl_xor_sync(~0u, lb, 1);
    lb += __shfl_xor_sync(~0u, lb, 2);
    const float ia = 1.f / la, ib = 1.f / lb;
    float* On = out + (size_t)n * CD * HW + q0;
#pragma unroll
    for (int j = 0; j < 8; j++) {
        int cb2 = j * 8 + 2 * tq;
        On[(size_t)cb2 * HW + row_a] = o[j][0] * ia;
        On[(size_t)(cb2 + 1) * HW + row_a] = o[j][1] * ia;
        On[(size_t)cb2 * HW + row_b] = o[j][2] * ib;
        On[(size_t)(cb2 + 1) * HW + row_b] = o[j][3] * ib;
    }
}

extern "C" void kernel_launch(void* const* d_in, const int* in_sizes, int n_in,
                              void* d_out, int out_size) {
    const float* X = (const float*)d_in[0];
    float* out = (float*)d_out;
    cudaFuncSetAttribute(attn_mma, cudaFuncAttributeMaxDynamicSharedMemorySize, SMEM_TOTAL);
    convert_kernel<<<(NB * CD * HW / 4) / 256, 256>>>(X);
    fragk_kernel<<<NB * 512 * 4 * 32 / 256, 256>>>(X);
    fragq_kernel<<<NB * 256 * 4 * 32 / 256, 256>>>(X);
    attn_mma<<<dim3(HW / BM, NB), 128, SMEM_TOTAL>>>(out);
}

// round 11
// speedup vs baseline: 1.9543x; 1.9543x over previous
#include <cuda_runtime.h>
#include <cuda_fp16.h>
#include <cstdint>

#define HW 4096
#define CD 64
#define BM 64
#define BN 64
#define NT (HW / BN)
#define NB 8
#define RB 72
#define RBB 144
#define HALF_BYTES (64 * RBB)     // hi or lo sub-tile = 9216B
#define KVBUF (2 * HALF_BYTES)    // 18432B
#define SMEM_TOTAL (3 * KVBUF)    // 55296B -> 4 CTAs/SM

__device__ __align__(16) __half g_FH[NB * CD * HW];
__device__ __align__(16) __half g_FL[NB * CD * HW];

__device__ __forceinline__ uint32_t smem_u32(const void* p) {
    uint32_t a;
    asm("{ .reg .u64 t; cvta.to.shared.u64 t, %1; cvt.u32.u64 %0, t; }" : "=r"(a) : "l"(p));
    return a;
}
__device__ __forceinline__ void ldsm4(uint32_t addr, uint32_t* r) {
    asm volatile("ldmatrix.sync.aligned.m8n8.x4.shared.b16 {%0,%1,%2,%3}, [%4];"
                 : "=r"(r[0]), "=r"(r[1]), "=r"(r[2]), "=r"(r[3]) : "r"(addr));
}
__device__ __forceinline__ void ldsm4t(uint32_t addr, uint32_t* r) {
    asm volatile("ldmatrix.sync.aligned.m8n8.x4.trans.shared.b16 {%0,%1,%2,%3}, [%4];"
                 : "=r"(r[0]), "=r"(r[1]), "=r"(r[2]), "=r"(r[3]) : "r"(addr));
}
__device__ __forceinline__ void mma_f16(float* d, const uint32_t* a, uint32_t b0, uint32_t b1) {
    asm volatile(
        "mma.sync.aligned.m16n8k16.row.col.f32.f16.f16.f32 "
        "{%0,%1,%2,%3}, {%4,%5,%6,%7}, {%8,%9}, {%0,%1,%2,%3};"
        : "+f"(d[0]), "+f"(d[1]), "+f"(d[2]), "+f"(d[3])
        : "r"(a[0]), "r"(a[1]), "r"(a[2]), "r"(a[3]), "r"(b0), "r"(b1));
}
#define CP16(dst, src) asm volatile("cp.async.cg.shared.global [%0], [%1], 16;" :: "r"(dst), "l"(src))
#define CP_COMMIT()    asm volatile("cp.async.commit_group;" ::: "memory")
#define CP_WAIT0()     asm volatile("cp.async.wait_group 0;" ::: "memory")
#define CP_WAIT1()     asm volatile("cp.async.wait_group 1;" ::: "memory")

__device__ __forceinline__ uint32_t pkf16(float a, float b) {
    uint32_t r;
    asm("cvt.rn.f16x2.f32 %0, %1, %2;" : "=r"(r) : "f"(b), "f"(a));
    return r;
}

// ---------------- pre-kernel: split X into fp16 hi/lo global arrays ----------------
__global__ __launch_bounds__(256) void convert_kernel(const float* __restrict__ X) {
    size_t i = (size_t)blockIdx.x * 256 + threadIdx.x;
    float4 v = reinterpret_cast<const float4*>(X)[i];
    __half hx = __float2half_rn(v.x), hy = __float2half_rn(v.y);
    __half hz = __float2half_rn(v.z), hw = __float2half_rn(v.w);
    __half lx = __float2half_rn(v.x - __half2float(hx));
    __half ly = __float2half_rn(v.y - __half2float(hy));
    __half lz = __float2half_rn(v.z - __half2float(hz));
    __half lw = __float2half_rn(v.w - __half2float(hw));
    uint2 h, l;
    h.x = (uint32_t)__half_as_ushort(hx) | ((uint32_t)__half_as_ushort(hy) << 16);
    h.y = (uint32_t)__half_as_ushort(hz) | ((uint32_t)__half_as_ushort(hw) << 16);
    l.x = (uint32_t)__half_as_ushort(lx) | ((uint32_t)__half_as_ushort(ly) << 16);
    l.y = (uint32_t)__half_as_ushort(lz) | ((uint32_t)__half_as_ushort(lw) << 16);
    reinterpret_cast<uint2*>(g_FH)[i] = h;
    reinterpret_cast<uint2*>(g_FL)[i] = l;
}

// ---------------- main attention kernel: half-tile software pipeline ----------------
__global__ __launch_bounds__(128, 4) void attn_mma(float* __restrict__ out) {
    extern __shared__ __align__(128) char SM[];
    const uint32_t smb = smem_u32(SM);

    const int n = blockIdx.y;
    const int q0 = blockIdx.x * BM;
    const int tid = threadIdx.x;
    const int lane = tid & 31;
    const int wid = tid >> 5;          // warp owns q rows wid*16 .. +15
    const int g = lane >> 2, tq = lane & 3;
    const int r8 = lane & 7, sel = lane >> 3;

    const char* FHn = (const char*)(g_FH + (size_t)n * CD * HW);
    const char* FLn = (const char*)(g_FL + (size_t)n * CD * HW);

    auto stage = [&](uint32_t bufoff, int col0) {
#pragma unroll
        for (int i = 0; i < 8; i++) {
            int idx = i * 128 + tid;
            int half = idx >> 9;
            int c = (idx >> 3) & 63;
            int ch = idx & 7;
            const char* base = half ? FLn : FHn;
            const char* src = base + ((size_t)c * HW + col0 + ch * 8) * 2;
            uint32_t dst = smb + bufoff + half * HALF_BYTES + c * RBB + ch * 16;
            CP16(dst, src);
        }
    };

    // ---- prologue: Q via buf0 ----
    stage(0, q0);
    CP_COMMIT();
    CP_WAIT0();
    __syncthreads();
    uint32_t qh[4][4], ql[4][4];
    {
        const uint32_t lo = ((sel >> 1) * 8 + r8) * RBB + (wid * 16 + (sel & 1) * 8) * 2;
#pragma unroll
        for (int ch = 0; ch < 4; ch++) {
            ldsm4t(smb + ch * 16 * RBB + lo, qh[ch]);
            ldsm4t(smb + HALF_BYTES + ch * 16 * RBB + lo, ql[ch]);
        }
    }
    __syncthreads();
    stage(0, 0);               CP_COMMIT();
    stage(KVBUF, BN);          CP_COMMIT();
    stage(2 * KVBUF, 2 * BN);  CP_COMMIT();
    CP_WAIT1();                // tiles 0,1 resident; tile 2 in flight
    __syncthreads();

    const int row_a = wid * 16 + g, row_b = row_a + 8;
    const uint32_t g1off = ((sel & 1) * 8 + r8) * RBB + ((sel >> 1) * 8) * 2;
    const uint32_t g2off = ((sel >> 1) * 8 + r8) * RBB + ((sel & 1) * 8) * 2;

    float o[8][4];
#pragma unroll
    for (int j = 0; j < 8; j++)
#pragma unroll
        for (int r = 0; r < 4; r++) o[j][r] = 0.f;
    float la = 0.f, lb = 0.f;
    float ma = -1e30f, mb = -1e30f;
    float sA[4][4], sB[4][4];

    // gemm1 for one 32-key half (kp=0/1): 12 ldsm + 48 MMA into sn
    auto gemm1half = [&](uint32_t vb, int kp, float (&sn)[4][4]) {
#pragma unroll
        for (int j = 0; j < 4; j++)
#pragma unroll
            for (int r = 0; r < 4; r++) sn[j][r] = 0.f;
#pragma unroll
        for (int ch = 0; ch < 4; ch++) {
            const uint32_t base = vb + g1off + ch * 16 * RBB + kp * 64;
            uint32_t bh0[4], bl0[4], bh1[4], bl1[4];
            ldsm4t(base, bh0);
            ldsm4t(base + HALF_BYTES, bl0);
            ldsm4t(base + 32, bh1);
            ldsm4t(base + 32 + HALF_BYTES, bl1);
            mma_f16(sn[0], qh[ch], bh0[0], bh0[1]);
            mma_f16(sn[1], qh[ch], bh0[2], bh0[3]);
            mma_f16(sn[2], qh[ch], bh1[0], bh1[1]);
            mma_f16(sn[3], qh[ch], bh1[2], bh1[3]);
            mma_f16(sn[0], qh[ch], bl0[0], bl0[1]);
            mma_f16(sn[1], qh[ch], bl0[2], bl0[3]);
            mma_f16(sn[2], qh[ch], bl1[0], bl1[1]);
            mma_f16(sn[3], qh[ch], bl1[2], bl1[3]);
            mma_f16(sn[0], ql[ch], bh0[0], bh0[1]);
            mma_f16(sn[1], ql[ch], bh0[2], bh0[3]);
            mma_f16(sn[2], ql[ch], bh1[0], bh1[1]);
            mma_f16(sn[3], ql[ch], bh1[2], bh1[3]);
        }
    };

    // online softmax for one half (branchless rescale; exp(0)=1 when max unchanged)
    auto softhalf = [&](float (&sc)[4][4], uint32_t (&pf)[2][4]) {
        float am = fmaxf(fmaxf(sc[0][0], sc[0][1]), fmaxf(sc[1][0], sc[1][1]));
        am = fmaxf(am, fmaxf(fmaxf(sc[2][0], sc[2][1]), fmaxf(sc[3][0], sc[3][1])));
        float bm = fmaxf(fmaxf(sc[0][2], sc[0][3]), fmaxf(sc[1][2], sc[1][3]));
        bm = fmaxf(bm, fmaxf(fmaxf(sc[2][2], sc[2][3]), fmaxf(sc[3][2], sc[3][3])));
        am = fmaxf(am, __shfl_xor_sync(~0u, am, 1));
        am = fmaxf(am, __shfl_xor_sync(~0u, am, 2));
        bm = fmaxf(bm, __shfl_xor_sync(~0u, bm, 1));
        bm = fmaxf(bm, __shfl_xor_sync(~0u, bm, 2));
        float man = fmaxf(ma, am), mbn = fmaxf(mb, bm);
        float ca = __expf(ma - man), cb = __expf(mb - mbn);
        ma = man;
        mb = mbn;
        la *= ca;
        lb *= cb;
#pragma unroll
        for (int j = 0; j < 8; j++) {
            o[j][0] *= ca;
            o[j][1] *= ca;
            o[j][2] *= cb;
            o[j][3] *= cb;
        }
#pragma unroll
        for (int kc2 = 0; kc2 < 2; kc2++) {
            float e0 = __expf(sc[2 * kc2][0] - ma), e1 = __expf(sc[2 * kc2][1] - ma);
            float e2 = __expf(sc[2 * kc2][2] - mb), e3 = __expf(sc[2 * kc2][3] - mb);
            float e4 = __expf(sc[2 * kc2 + 1][0] - ma), e5 = __expf(sc[2 * kc2 + 1][1] - ma);
            float e6 = __expf(sc[2 * kc2 + 1][2] - mb), e7 = __expf(sc[2 * kc2 + 1][3] - mb);
            la += e0 + e1 + e4 + e5;
            lb += e2 + e3 + e6 + e7;
            pf[kc2][0] = pkf16(e0, e1);
            pf[kc2][1] = pkf16(e2, e3);
            pf[kc2][2] = pkf16(e4, e5);
            pf[kc2][3] = pkf16(e6, e7);
        }
    };

    // gemm2 for one half: 8 ldsm + 16 MMA into o
    auto gemm2half = [&](uint32_t vb, int hb, uint32_t (&pf)[2][4]) {
#pragma unroll
        for (int kc2 = 0; kc2 < 2; kc2++) {
            const int kc = 2 * hb + kc2;
#pragma unroll
            for (int mp = 0; mp < 2; mp++) {
                const uint32_t ba = vb + g2off + (2 * mp) * 16 * RBB + kc * 32;
                const uint32_t bb = ba + 16 * RBB;
                uint32_t bfa[4], bfb[4];
                ldsm4(ba, bfa);
                ldsm4(bb, bfb);
                mma_f16(o[4 * mp], pf[kc2], bfa[0], bfa[1]);
                mma_f16(o[4 * mp + 1], pf[kc2], bfa[2], bfa[3]);
                mma_f16(o[4 * mp + 2], pf[kc2], bfb[0], bfb[1]);
                mma_f16(o[4 * mp + 3], pf[kc2], bfb[2], bfb[3]);
            }
        }
    };

    int b0 = 0, b1 = 1, b2 = 2;
    gemm1half(smb, 0, sA);   // S(tile0, half0)

    for (int t = 0; t < NT - 1; t++) {
        const uint32_t vb = smb + (uint32_t)b0 * KVBUF;
        const uint32_t vn = smb + (uint32_t)b1 * KVBUF;
        uint32_t pf[2][4];
        // half A: gemm1(next = same tile, kp1) || softmax(half0) ; gemm2(half0)
        gemm1half(vb, 1, sB);
        softhalf(sA, pf);
        gemm2half(vb, 0, pf);
        // half B: gemm1(next = tile t+1, kp0) || softmax(half1) ; gemm2(half1)
        gemm1half(vn, 0, sA);
        softhalf(sB, pf);
        gemm2half(vb, 1, pf);
        __syncthreads();                      // all warps done with buf b0
        if (t + 3 < NT) stage((uint32_t)b0 * KVBUF, (t + 3) * BN);
        CP_COMMIT();
        CP_WAIT1();                           // tile t+2 resident
        int tmp = b0; b0 = b1; b1 = b2; b2 = tmp;
    }
    // t = NT-1 (tile 63)
    {
        const uint32_t vb = smb + (uint32_t)b0 * KVBUF;
        uint32_t pf[2][4];
        gemm1half(vb, 1, sB);
        softhalf(sA, pf);
        gemm2half(vb, 0, pf);
        softhalf(sB, pf);
        gemm2half(vb, 1, pf);
    }

    // ---- epilogue: rows warp-local -> normalize + store ----
    la += __shfl_xor_sync(~0u, la, 1);
    la += __shfl_xor_sync(~0u, la, 2);
    lb += __shfl_xor_sync(~0u, lb, 1);
    lb += __shfl_xor_sync(~0u, lb, 2);
    const float ia = 1.f / la, ib = 1.f / lb;
    float* On = out + (size_t)n * CD * HW + q0;
#pragma unroll
    for (int j = 0; j < 8; j++) {
        int cb2 = j * 8 + 2 * tq;
        On[(size_t)cb2 * HW + row_a] = o[j][0] * ia;
        On[(size_t)(cb2 + 1) * HW + row_a] = o[j][1] * ia;
        On[(size_t)cb2 * HW + row_b] = o[j][2] * ib;
        On[(size_t)(cb2 + 1) * HW + row_b] = o[j][3] * ib;
    }
}

extern "C" void kernel_launch(void* const* d_in, const int* in_sizes, int n_in,
                              void* d_out, int out_size) {
    const float* X = (const float*)d_in[0];
    float* out = (float*)d_out;
    cudaFuncSetAttribute(attn_mma, cudaFuncAttributeMaxDynamicSharedMemorySize, SMEM_TOTAL);
    convert_kernel<<<(NB * CD * HW / 4) / 256, 256>>>(X);
    attn_mma<<<dim3(HW / BM, NB), 128, SMEM_TOTAL>>>(out);
}

// round 12
// speedup vs baseline: 2.2963x; 1.1750x over previous
#include <cuda_runtime.h>
#include <cuda_fp16.h>
#include <cstdint>

#define HW 4096
#define CD 64
#define BM 64
#define BN 64
#define NT (HW / BN)
#define NB 8
#define RB 72                    // padded row length (16b elems) -> conflict-free ldmatrix
#define RBB (RB * 2)             // row bytes = 144
#define HALF_BYTES (64 * RBB)    // one sub-tile (hi or lo) = 9216B
#define KVBUF (2 * HALF_BYTES)   // hi+lo = 18432B
#define QOFF (2 * KVBUF)         // Q region after 2 KV buffers
#define SMEM_TOTAL (3 * KVBUF)   // 55296B
#define L2E 1.4426950408889634f

__device__ __align__(16) __half g_FH[NB * CD * HW];
__device__ __align__(16) __half g_FL[NB * CD * HW];
__device__ float g_negM[NB * HW];   // -(||x_q||^2 + 1) * log2(e)

__device__ __forceinline__ uint32_t smem_u32(const void* p) {
    uint32_t a;
    asm("{ .reg .u64 t; cvta.to.shared.u64 t, %1; cvt.u32.u64 %0, t; }" : "=r"(a) : "l"(p));
    return a;
}
__device__ __forceinline__ void ldsm4(uint32_t addr, uint32_t* r) {
    asm volatile("ldmatrix.sync.aligned.m8n8.x4.shared.b16 {%0,%1,%2,%3}, [%4];"
                 : "=r"(r[0]), "=r"(r[1]), "=r"(r[2]), "=r"(r[3]) : "r"(addr));
}
__device__ __forceinline__ void ldsm4t(uint32_t addr, uint32_t* r) {
    asm volatile("ldmatrix.sync.aligned.m8n8.x4.trans.shared.b16 {%0,%1,%2,%3}, [%4];"
                 : "=r"(r[0]), "=r"(r[1]), "=r"(r[2]), "=r"(r[3]) : "r"(addr));
}
__device__ __forceinline__ void mma_f16(float* d, const uint32_t* a, uint32_t b0, uint32_t b1) {
    asm volatile(
        "mma.sync.aligned.m16n8k16.row.col.f32.f16.f16.f32 "
        "{%0,%1,%2,%3}, {%4,%5,%6,%7}, {%8,%9}, {%0,%1,%2,%3};"
        : "+f"(d[0]), "+f"(d[1]), "+f"(d[2]), "+f"(d[3])
        : "r"(a[0]), "r"(a[1]), "r"(a[2]), "r"(a[3]), "r"(b0), "r"(b1));
}
#define CP16(dst, src) asm volatile("cp.async.cg.shared.global [%0], [%1], 16;" :: "r"(dst), "l"(src))
#define CP_COMMIT()    asm volatile("cp.async.commit_group;" ::: "memory")
#define CP_WAIT1()     asm volatile("cp.async.wait_group 1;" ::: "memory")
#define CP_WAIT2()     asm volatile("cp.async.wait_group 2;" ::: "memory")

__device__ __forceinline__ uint32_t pkf16(float a, float b) {
    uint32_t r;
    asm("cvt.rn.f16x2.f32 %0, %1, %2;" : "=r"(r) : "f"(b), "f"(a));
    return r;
}
__device__ __forceinline__ float ex2(float x) {
    float r;
    asm("ex2.approx.ftz.f32 %0, %1;" : "=f"(r) : "f"(x));
    return r;
}

// ---------------- pre-kernel 1: split X into fp16 hi/lo global arrays ----------------
__global__ __launch_bounds__(256) void convert_kernel(const float* __restrict__ X) {
    size_t i = (size_t)blockIdx.x * 256 + threadIdx.x;
    float4 v = reinterpret_cast<const float4*>(X)[i];
    __half hx = __float2half_rn(v.x), hy = __float2half_rn(v.y);
    __half hz = __float2half_rn(v.z), hw = __float2half_rn(v.w);
    __half lx = __float2half_rn(v.x - __half2float(hx));
    __half ly = __float2half_rn(v.y - __half2float(hy));
    __half lz = __float2half_rn(v.z - __half2float(hz));
    __half lw = __float2half_rn(v.w - __half2float(hw));
    uint2 h, l;
    h.x = (uint32_t)__half_as_ushort(hx) | ((uint32_t)__half_as_ushort(hy) << 16);
    h.y = (uint32_t)__half_as_ushort(hz) | ((uint32_t)__half_as_ushort(hw) << 16);
    l.x = (uint32_t)__half_as_ushort(lx) | ((uint32_t)__half_as_ushort(ly) << 16);
    l.y = (uint32_t)__half_as_ushort(lz) | ((uint32_t)__half_as_ushort(lw) << 16);
    reinterpret_cast<uint2*>(g_FH)[i] = h;
    reinterpret_cast<uint2*>(g_FL)[i] = l;
}

// ---------------- pre-kernel 2: diagonal softmax shift -(||x_q||^2+1)*log2e ----------------
__global__ __launch_bounds__(256) void norm_kernel(const float* __restrict__ X) {
    const int n = blockIdx.y;
    const int q = blockIdx.x * 256 + threadIdx.x;
    const float* Xn = X + (size_t)n * CD * HW;
    float s = 0.f;
#pragma unroll
    for (int c = 0; c < CD; c++) {
        float v = Xn[c * HW + q];
        s = fmaf(v, v, s);
    }
    g_negM[n * HW + q] = -(s + 1.0f) * L2E;
}

// ---------------- main attention kernel: 4 warps, each 16q x 64k, static shift ----------------
__global__ __launch_bounds__(128, 4) void attn_mma(float* __restrict__ out) {
    extern __shared__ __align__(128) char SM[];
    const uint32_t smb = smem_u32(SM);

    const int n = blockIdx.y;
    const int q0 = blockIdx.x * BM;
    const int tid = threadIdx.x;
    const int lane = tid & 31;
    const int wid = tid >> 5;          // warp owns q rows wid*16 .. +15
    const int g = lane >> 2, tq = lane & 3;
    const int r8 = lane & 7, sel = lane >> 3;

    const char* FHn = (const char*)(g_FH + (size_t)n * CD * HW);
    const char* FLn = (const char*)(g_FL + (size_t)n * CD * HW);

    auto stage = [&](uint32_t bufoff, int col0) {
#pragma unroll
        for (int i = 0; i < 8; i++) {
            int idx = i * 128 + tid;
            int half = idx >> 9;
            int c = (idx >> 3) & 63;
            int ch = idx & 7;
            const char* base = half ? FLn : FHn;
            const char* src = base + ((size_t)c * HW + col0 + ch * 8) * 2;
            uint32_t dst = smb + bufoff + half * HALF_BYTES + c * RBB + ch * 16;
            CP16(dst, src);
        }
    };

    stage(QOFF, q0);     CP_COMMIT();   // Q
    stage(0, 0);         CP_COMMIT();   // KV tile 0
    stage(KVBUF, BN);    CP_COMMIT();   // KV tile 1
    CP_WAIT2();          // Q resident
    __syncthreads();

    // ---- Q A-fragments (trans ldmatrix from [c][q] layout), hi+lo fp16 ----
    uint32_t qh[4][4], ql[4][4];
    {
        const uint32_t qb = smb + QOFF;
        const uint32_t lo = ((sel >> 1) * 8 + r8) * RBB + (wid * 16 + (sel & 1) * 8) * 2;
#pragma unroll
        for (int ch = 0; ch < 4; ch++) {
            ldsm4t(qb + ch * 16 * RBB + lo, qh[ch]);
            ldsm4t(qb + HALF_BYTES + ch * 16 * RBB + lo, ql[ch]);
        }
    }

    const int row_a = wid * 16 + g, row_b = row_a + 8;
    const float negMa = g_negM[n * HW + q0 + row_a];
    const float negMb = g_negM[n * HW + q0 + row_b];

    float o[8][4];
#pragma unroll
    for (int j = 0; j < 8; j++)
#pragma unroll
        for (int r = 0; r < 4; r++) o[j][r] = 0.f;
    float la = 0.f, lb = 0.f;

    const uint32_t g1off = ((sel & 1) * 8 + r8) * RBB + ((sel >> 1) * 8) * 2;
    const uint32_t g2off = ((sel >> 1) * 8 + r8) * RBB + ((sel & 1) * 8) * 2;

    for (int t = 0; t < NT; t++) {
        CP_WAIT1();          // tile t resident (t+1 may still be in flight)
        __syncthreads();
        const uint32_t vb = smb + (t & 1) * KVBUF;

        // ---- gemm1: S(16x64) = Q Kt, fp16 3 split passes ----
        float s[8][4];
#pragma unroll
        for (int j = 0; j < 8; j++)
#pragma unroll
            for (int r = 0; r < 4; r++) s[j][r] = 0.f;
#pragma unroll
        for (int ch = 0; ch < 4; ch++) {
            const uint32_t base = vb + g1off + ch * 16 * RBB;
#pragma unroll
            for (int kp = 0; kp < 2; kp++) {   // key-group pairs
                const uint32_t ka = base + (2 * kp) * 32;
                const uint32_t kb = ka + 32;
                uint32_t bh0[4], bl0[4], bh1[4], bl1[4];
                ldsm4t(ka, bh0);
                ldsm4t(ka + HALF_BYTES, bl0);
                ldsm4t(kb, bh1);
                ldsm4t(kb + HALF_BYTES, bl1);
                float* s0 = s[4 * kp], * s1 = s[4 * kp + 1];
                float* s2 = s[4 * kp + 2], * s3 = s[4 * kp + 3];
                mma_f16(s0, qh[ch], bh0[0], bh0[1]);
                mma_f16(s1, qh[ch], bh0[2], bh0[3]);
                mma_f16(s2, qh[ch], bh1[0], bh1[1]);
                mma_f16(s3, qh[ch], bh1[2], bh1[3]);
                mma_f16(s0, qh[ch], bl0[0], bl0[1]);
                mma_f16(s1, qh[ch], bl0[2], bl0[3]);
                mma_f16(s2, qh[ch], bl1[0], bl1[1]);
                mma_f16(s3, qh[ch], bl1[2], bl1[3]);
                mma_f16(s0, ql[ch], bh0[0], bh0[1]);
                mma_f16(s1, ql[ch], bh0[2], bh0[3]);
                mma_f16(s2, ql[ch], bh1[0], bh1[1]);
                mma_f16(s3, ql[ch], bh1[2], bh1[3]);
            }
        }

        // ---- static-shift softmax: P = exp2(S*log2e - M'), no max, no rescale ----
        uint32_t pf[4][4];
#pragma unroll
        for (int kc = 0; kc < 4; kc++) {
            float e0 = ex2(fmaf(s[2 * kc][0], L2E, negMa));
            float e1 = ex2(fmaf(s[2 * kc][1], L2E, negMa));
            float e2 = ex2(fmaf(s[2 * kc][2], L2E, negMb));
            float e3 = ex2(fmaf(s[2 * kc][3], L2E, negMb));
            float e4 = ex2(fmaf(s[2 * kc + 1][0], L2E, negMa));
            float e5 = ex2(fmaf(s[2 * kc + 1][1], L2E, negMa));
            float e6 = ex2(fmaf(s[2 * kc + 1][2], L2E, negMb));
            float e7 = ex2(fmaf(s[2 * kc + 1][3], L2E, negMb));
            la += e0 + e1 + e4 + e5;
            lb += e2 + e3 + e6 + e7;
            pf[kc][0] = pkf16(e0, e1);
            pf[kc][1] = pkf16(e2, e3);
            pf[kc][2] = pkf16(e4, e5);
            pf[kc][3] = pkf16(e6, e7);
        }

        // ---- gemm2: O(16x64) += P V, fp16 single pass ----
#pragma unroll
        for (int kc = 0; kc < 4; kc++) {
#pragma unroll
            for (int mp = 0; mp < 2; mp++) {
                const uint32_t ba = vb + g2off + (2 * mp) * 16 * RBB + kc * 32;
                const uint32_t bb = ba + 16 * RBB;
                uint32_t bfa[4], bfb[4];
                ldsm4(ba, bfa);
                ldsm4(bb, bfb);
                mma_f16(o[4 * mp], pf[kc], bfa[0], bfa[1]);
                mma_f16(o[4 * mp + 1], pf[kc], bfa[2], bfa[3]);
                mma_f16(o[4 * mp + 2], pf[kc], bfb[0], bfb[1]);
                mma_f16(o[4 * mp + 3], pf[kc], bfb[2], bfb[3]);
            }
        }
        __syncthreads();     // all warps done reading buf t%2
        if (t + 2 < NT) stage((t & 1) * KVBUF, (t + 2) * BN);
        CP_COMMIT();
    }

    // ---- epilogue: rows warp-local -> normalize + store ----
    la += __shfl_xor_sync(~0u, la, 1);
    la += __shfl_xor_sync(~0u, la, 2);
    lb += __shfl_xor_sync(~0u, lb, 1);
    lb += __shfl_xor_sync(~0u, lb, 2);
    const float ia = 1.f / la, ib = 1.f / lb;
    float* On = out + (size_t)n * CD * HW + q0;
#pragma unroll
    for (int j = 0; j < 8; j++) {
        int cb2 = j * 8 + 2 * tq;
        On[(size_t)cb2 * HW + row_a] = o[j][0] * ia;
        On[(size_t)(cb2 + 1) * HW + row_a] = o[j][1] * ia;
        On[(size_t)cb2 * HW + row_b] = o[j][2] * ib;
        On[(size_t)(cb2 + 1) * HW + row_b] = o[j][3] * ib;
    }
}

extern "C" void kernel_launch(void* const* d_in, const int* in_sizes, int n_in,
                              void* d_out, int out_size) {
    const float* X = (const float*)d_in[0];
    float* out = (float*)d_out;
    cudaFuncSetAttribute(attn_mma, cudaFuncAttributeMaxDynamicSharedMemorySize, SMEM_TOTAL);
    convert_kernel<<<(NB * CD * HW / 4) / 256, 256>>>(X);
    norm_kernel<<<dim3(HW / 256, NB), 256>>>(X);
    attn_mma<<<dim3(HW / BM, NB), 128, SMEM_TOTAL>>>(out);
}